// round 12
// baseline (speedup 1.0000x reference)
#include <cuda_runtime.h>
#include <cstdint>
#include <math.h>
#include <math_constants.h>

// TopLoss: three 8M x 2 fp32 diagrams.
//   l = dgm[:,0] - dgm[:,1], non-finite -> 0
//   top1 = max(l0); t01 = 1 - top1^2; t0 = sumsq(l0) - top1^2
//   t1 = sumsq(l1); t2 = sumsq(l2); loss = t01 + t0 + t1 + t2
// Output: (loss, t01, t0, t1, t2) as 5 fp32.
//
// cp.async 2-stage pipeline: in-flight bytes live in SMEM, not registers
// (96 KB/SM in flight vs 24 KB with plain LDG at regs=32). Each thread
// stages and consumes only its own 48-byte slot -> per-thread cp.async
// groups, no __syncthreads in the main loop. Last-CTA finalize.
// NOTE: static smem (~260 B) + 48 KB dynamic exceeds the default 48 KB
// combined cap -> must opt in via cudaFuncAttributeMaxDynamicSharedMemorySize.

#define NPAIRS   (8 * 1024 * 1024)
#define NVEC     (NPAIRS / 2)          // 4194304 float4 per array
#define NTHR     512
#define NBLK     592                   // 148 SMs * 4 CTAs, one resident wave
#define STRIDE   (NBLK * NTHR)         // 303104
#define NFULL    13                    // full strides (all threads valid)
#define NREM     (NVEC - NFULL * STRIDE)  // 253952
#define NITER    14                    // 13 full + 1 predicated partial
#define NWARP    (NTHR / 32)           // 16
#define STAGE_BYTES (NTHR * 48)        // one stage: 512 threads * 3 float4

// Per-block partials: {sumsq0, sumsq1, sumsq2, max_l0}
__device__ float4       g_partial[NBLK];
__device__ unsigned int g_count = 0;

__device__ __forceinline__ float bar_len(float a, float b) {
    float l = a - b;
    return isfinite(l) ? l : 0.0f;
}

__device__ __forceinline__ void cp16(unsigned int dst_smem, const void* src) {
    asm volatile("cp.async.cg.shared.global [%0], [%1], 16;"
                 :: "r"(dst_smem), "l"(src));
}

__device__ __forceinline__ void acc_sum(const float4& v, float& s) {
    float la = bar_len(v.x, v.y);
    float lb = bar_len(v.z, v.w);
    s = fmaf(la, la, s);
    s = fmaf(lb, lb, s);
}

__device__ __forceinline__ void acc_sum_max(const float4& v, float& s, float& m) {
    float la = bar_len(v.x, v.y);
    float lb = bar_len(v.z, v.w);
    s = fmaf(la, la, s);
    s = fmaf(lb, lb, s);
    m = fmaxf(m, fmaxf(la, lb));
}

__device__ __forceinline__ void warp_reduce4(float& s0, float& s1, float& s2, float& m) {
    #pragma unroll
    for (int o = 16; o > 0; o >>= 1) {
        s0 += __shfl_down_sync(0xFFFFFFFFu, s0, o);
        s1 += __shfl_down_sync(0xFFFFFFFFu, s1, o);
        s2 += __shfl_down_sync(0xFFFFFFFFu, s2, o);
        m   = fmaxf(m, __shfl_down_sync(0xFFFFFFFFu, m, o));
    }
}

extern __shared__ float4 s_pipe[];   // [2][NTHR][3] float4

__global__ void __launch_bounds__(NTHR, 4)
toploss_fused(const float4* __restrict__ d0,
              const float4* __restrict__ d1,
              const float4* __restrict__ d2,
              float* __restrict__ out) {
    const int tid  = threadIdx.x;
    const int base = blockIdx.x * NTHR + tid;
    const bool rem_valid = (base < NREM);

    // Shared-space byte address of this thread's slot in stage 0.
    const unsigned int slot0 =
        (unsigned int)__cvta_generic_to_shared(s_pipe) + (unsigned int)tid * 48u;

    float s0 = 0.0f, s1 = 0.0f, s2 = 0.0f;
    float m = -CUDART_INF_F;

    // ---- prologue: issue stage for k=0 (always valid) ----
    {
        cp16(slot0,       d0 + base);
        cp16(slot0 + 16u, d1 + base);
        cp16(slot0 + 32u, d2 + base);
        asm volatile("cp.async.commit_group;");
    }

    // ---- 2-stage software pipeline (no barriers: per-thread slots only) ----
    #pragma unroll
    for (int k = 0; k < NITER; k++) {
        if (k + 1 < NITER) {
            const bool v = (k + 1 < NFULL) || rem_valid;
            const unsigned int d = slot0 + (unsigned int)((k + 1) & 1) * STAGE_BYTES;
            const int idx = base + (k + 1) * STRIDE;
            if (v) {
                cp16(d,       d0 + idx);
                cp16(d + 16u, d1 + idx);
                cp16(d + 32u, d2 + idx);
            }
            asm volatile("cp.async.commit_group;");
            asm volatile("cp.async.wait_group 1;");
        } else {
            asm volatile("cp.async.wait_group 0;");
        }

        if (k < NFULL || rem_valid) {
            const float4* slot = s_pipe + ((size_t)(k & 1) * NTHR + tid) * 3;
            float4 v0 = slot[0];
            float4 v1 = slot[1];
            float4 v2 = slot[2];
            acc_sum_max(v0, s0, m);
            acc_sum(v1, s1);
            acc_sum(v2, s2);
        }
    }

    // ---- intra-block reduce ----
    warp_reduce4(s0, s1, s2, m);

    __shared__ float sh0[NWARP], sh1[NWARP], sh2[NWARP], shm[NWARP];
    int lane = tid & 31;
    int warp = tid >> 5;
    if (lane == 0) { sh0[warp] = s0; sh1[warp] = s1; sh2[warp] = s2; shm[warp] = m; }
    __syncthreads();

    if (warp == 0) {
        s0 = (lane < NWARP) ? sh0[lane] : 0.0f;
        s1 = (lane < NWARP) ? sh1[lane] : 0.0f;
        s2 = (lane < NWARP) ? sh2[lane] : 0.0f;
        m  = (lane < NWARP) ? shm[lane] : -CUDART_INF_F;
        #pragma unroll
        for (int o = 8; o > 0; o >>= 1) {   // NWARP == 16
            s0 += __shfl_down_sync(0xFFFFFFFFu, s0, o);
            s1 += __shfl_down_sync(0xFFFFFFFFu, s1, o);
            s2 += __shfl_down_sync(0xFFFFFFFFu, s2, o);
            m   = fmaxf(m, __shfl_down_sync(0xFFFFFFFFu, m, o));
        }
        if (lane == 0) {
            g_partial[blockIdx.x] = make_float4(s0, s1, s2, m);
            __threadfence();  // release: partial visible before counter bump
        }
    }
    __syncthreads();

    // ---- last-CTA finalize ----
    __shared__ unsigned int s_ticket;
    if (tid == 0) s_ticket = atomicAdd(&g_count, 1u);
    __syncthreads();
    if (s_ticket != NBLK - 1) return;

    s0 = 0.0f; s1 = 0.0f; s2 = 0.0f; m = -CUDART_INF_F;
    for (int i = tid; i < NBLK; i += NTHR) {
        float4 p = g_partial[i];
        s0 += p.x; s1 += p.y; s2 += p.z;
        m = fmaxf(m, p.w);
    }

    warp_reduce4(s0, s1, s2, m);

    if (lane == 0) { sh0[warp] = s0; sh1[warp] = s1; sh2[warp] = s2; shm[warp] = m; }
    __syncthreads();

    if (warp == 0) {
        s0 = (lane < NWARP) ? sh0[lane] : 0.0f;
        s1 = (lane < NWARP) ? sh1[lane] : 0.0f;
        s2 = (lane < NWARP) ? sh2[lane] : 0.0f;
        m  = (lane < NWARP) ? shm[lane] : -CUDART_INF_F;
        #pragma unroll
        for (int o = 8; o > 0; o >>= 1) {
            s0 += __shfl_down_sync(0xFFFFFFFFu, s0, o);
            s1 += __shfl_down_sync(0xFFFFFFFFu, s1, o);
            s2 += __shfl_down_sync(0xFFFFFFFFu, s2, o);
            m   = fmaxf(m, __shfl_down_sync(0xFFFFFFFFu, m, o));
        }
        if (lane == 0) {
            float m2  = m * m;
            float t01 = 1.0f - m2;
            float t0  = s0 - m2;
            out[0] = t01 + t0 + s1 + s2;  // loss
            out[1] = t01;
            out[2] = t0;
            out[3] = s1;
            out[4] = s2;
            g_count = 0;                  // reset for next graph replay
        }
    }
}

extern "C" void kernel_launch(void* const* d_in, const int* in_sizes, int n_in,
                              void* d_out, int out_size) {
    const float4* d0 = (const float4*)d_in[0];
    const float4* d1 = (const float4*)d_in[1];
    const float4* d2 = (const float4*)d_in[2];
    const int smem_bytes = 2 * STAGE_BYTES;   // 49152 = 48 KB dynamic

    // Opt in: static (~260 B) + 48 KB dynamic exceeds the default 48 KB
    // combined cap. Non-stream host API: capture-safe, idempotent.
    cudaFuncSetAttribute(toploss_fused,
                         cudaFuncAttributeMaxDynamicSharedMemorySize, smem_bytes);

    toploss_fused<<<NBLK, NTHR, smem_bytes>>>(d0, d1, d2, (float*)d_out);
}

// round 13
// speedup vs baseline: 1.4160x; 1.4160x over previous
#include <cuda_runtime.h>
#include <cstdint>
#include <math.h>
#include <math_constants.h>

// TopLoss: three 8M x 2 fp32 diagrams.
//   l = dgm[:,0] - dgm[:,1], non-finite -> 0
//   top1 = max(l0); t01 = 1 - top1^2; t0 = sumsq(l0) - top1^2
//   t1 = sumsq(l1); t2 = sumsq(l2); loss = t01 + t0 + t1 + t2
// Output: (loss, t01, t0, t1, t2) as 5 fp32.
//
// Single fused kernel, occupancy-first (regs<=32 via launch_bounds -> 64
// warps/SM). d0 stream software-pipelined one stride ahead: 4 outstanding
// LDG.128/warp during the consume window (~31 KB/SM in flight, under the
// L1tex queue cap) with no occupancy cost. Last-CTA finalize.

#define NPAIRS   (8 * 1024 * 1024)
#define NVEC     (NPAIRS / 2)          // 4194304 float4 per array
#define NTHR     512
#define NBLK     592                   // 148 SMs * 4 CTAs, one resident wave
#define STRIDE   (NBLK * NTHR)         // 303104
#define NFULL    13                    // full strides (all threads valid)
#define NREM     (NVEC - NFULL * STRIDE)  // 253952
#define NWARP    (NTHR / 32)           // 16

// Per-block partials: {sumsq0, sumsq1, sumsq2, max_l0}
__device__ float4       g_partial[NBLK];
__device__ unsigned int g_count = 0;

__device__ __forceinline__ float bar_len(float a, float b) {
    float l = a - b;
    return isfinite(l) ? l : 0.0f;
}

__device__ __forceinline__ void acc_sum(const float4& v, float& s) {
    float la = bar_len(v.x, v.y);
    float lb = bar_len(v.z, v.w);
    s = fmaf(la, la, s);
    s = fmaf(lb, lb, s);
}

__device__ __forceinline__ void acc_sum_max(const float4& v, float& s, float& m) {
    float la = bar_len(v.x, v.y);
    float lb = bar_len(v.z, v.w);
    s = fmaf(la, la, s);
    s = fmaf(lb, lb, s);
    m = fmaxf(m, fmaxf(la, lb));
}

__device__ __forceinline__ void warp_reduce4(float& s0, float& s1, float& s2, float& m) {
    #pragma unroll
    for (int o = 16; o > 0; o >>= 1) {
        s0 += __shfl_down_sync(0xFFFFFFFFu, s0, o);
        s1 += __shfl_down_sync(0xFFFFFFFFu, s1, o);
        s2 += __shfl_down_sync(0xFFFFFFFFu, s2, o);
        m   = fmaxf(m, __shfl_down_sync(0xFFFFFFFFu, m, o));
    }
}

__global__ void __launch_bounds__(NTHR, 4)
toploss_fused(const float4* __restrict__ d0,
              const float4* __restrict__ d1,
              const float4* __restrict__ d2,
              float* __restrict__ out) {
    const int tid  = threadIdx.x;
    const int base = blockIdx.x * NTHR + tid;
    const bool rem_valid = (base < NREM);

    float s0 = 0.0f, s1 = 0.0f, s2 = 0.0f;
    float m = -CUDART_INF_F;

    // prologue: prefetch d0 for iteration 0
    float4 next0 = d0[base];

    // ---- 13 full strides, d0 pipelined one ahead ----
    #pragma unroll
    for (int k = 0; k < NFULL; k++) {
        const int i = base + k * STRIDE;
        float4 cur0 = next0;
        float4 v1 = d1[i];
        float4 v2 = d2[i];
        if (k + 1 < NFULL) {
            next0 = d0[i + STRIDE];
        } else if (rem_valid) {
            next0 = d0[i + STRIDE];   // remainder prefetch
        }
        acc_sum_max(cur0, s0, m);
        acc_sum(v1, s1);
        acc_sum(v2, s2);
    }

    // ---- predicated remainder ----
    if (rem_valid) {
        const int i = base + NFULL * STRIDE;
        float4 v1 = d1[i];
        float4 v2 = d2[i];
        acc_sum_max(next0, s0, m);
        acc_sum(v1, s1);
        acc_sum(v2, s2);
    }

    // ---- intra-block reduce ----
    warp_reduce4(s0, s1, s2, m);

    __shared__ float sh0[NWARP], sh1[NWARP], sh2[NWARP], shm[NWARP];
    int lane = tid & 31;
    int warp = tid >> 5;
    if (lane == 0) { sh0[warp] = s0; sh1[warp] = s1; sh2[warp] = s2; shm[warp] = m; }
    __syncthreads();

    if (warp == 0) {
        s0 = (lane < NWARP) ? sh0[lane] : 0.0f;
        s1 = (lane < NWARP) ? sh1[lane] : 0.0f;
        s2 = (lane < NWARP) ? sh2[lane] : 0.0f;
        m  = (lane < NWARP) ? shm[lane] : -CUDART_INF_F;
        #pragma unroll
        for (int o = 8; o > 0; o >>= 1) {   // NWARP == 16
            s0 += __shfl_down_sync(0xFFFFFFFFu, s0, o);
            s1 += __shfl_down_sync(0xFFFFFFFFu, s1, o);
            s2 += __shfl_down_sync(0xFFFFFFFFu, s2, o);
            m   = fmaxf(m, __shfl_down_sync(0xFFFFFFFFu, m, o));
        }
        if (lane == 0) {
            g_partial[blockIdx.x] = make_float4(s0, s1, s2, m);
            __threadfence();  // release: partial visible before counter bump
        }
    }
    __syncthreads();

    // ---- last-CTA finalize ----
    __shared__ unsigned int s_ticket;
    if (tid == 0) s_ticket = atomicAdd(&g_count, 1u);
    __syncthreads();
    if (s_ticket != NBLK - 1) return;

    s0 = 0.0f; s1 = 0.0f; s2 = 0.0f; m = -CUDART_INF_F;
    for (int i = tid; i < NBLK; i += NTHR) {
        float4 p = g_partial[i];
        s0 += p.x; s1 += p.y; s2 += p.z;
        m = fmaxf(m, p.w);
    }

    warp_reduce4(s0, s1, s2, m);

    if (lane == 0) { sh0[warp] = s0; sh1[warp] = s1; sh2[warp] = s2; shm[warp] = m; }
    __syncthreads();

    if (warp == 0) {
        s0 = (lane < NWARP) ? sh0[lane] : 0.0f;
        s1 = (lane < NWARP) ? sh1[lane] : 0.0f;
        s2 = (lane < NWARP) ? sh2[lane] : 0.0f;
        m  = (lane < NWARP) ? shm[lane] : -CUDART_INF_F;
        #pragma unroll
        for (int o = 8; o > 0; o >>= 1) {
            s0 += __shfl_down_sync(0xFFFFFFFFu, s0, o);
            s1 += __shfl_down_sync(0xFFFFFFFFu, s1, o);
            s2 += __shfl_down_sync(0xFFFFFFFFu, s2, o);
            m   = fmaxf(m, __shfl_down_sync(0xFFFFFFFFu, m, o));
        }
        if (lane == 0) {
            float m2  = m * m;
            float t01 = 1.0f - m2;
            float t0  = s0 - m2;
            out[0] = t01 + t0 + s1 + s2;  // loss
            out[1] = t01;
            out[2] = t0;
            out[3] = s1;
            out[4] = s2;
            g_count = 0;                  // reset for next graph replay
        }
    }
}

extern "C" void kernel_launch(void* const* d_in, const int* in_sizes, int n_in,
                              void* d_out, int out_size) {
    const float4* d0 = (const float4*)d_in[0];
    const float4* d1 = (const float4*)d_in[1];
    const float4* d2 = (const float4*)d_in[2];
    toploss_fused<<<NBLK, NTHR>>>(d0, d1, d2, (float*)d_out);
}

// round 14
// speedup vs baseline: 1.5145x; 1.0696x over previous
#include <cuda_runtime.h>
#include <cstdint>
#include <math.h>
#include <math_constants.h>

// TopLoss: three 8M x 2 fp32 diagrams.
//   l = dgm[:,0] - dgm[:,1], non-finite -> 0
//   top1 = max(l0); t01 = 1 - top1^2; t0 = sumsq(l0) - top1^2
//   t1 = sumsq(l1); t2 = sumsq(l2); loss = t01 + t0 + t1 + t2
// Output: (loss, t01, t0, t1, t2) as 5 fp32.
//
// R8 loop body verbatim (proven fastest: 3 batched LDG.128 per iteration,
// 64 warps/SM, regs<=32). Only change vs R8: 296 CTAs x 1024 threads
// (launch_bounds(1024,2)) -> STRIDE identical (303104), memory pattern
// bit-identical, but half the CTAs => smaller last-CTA atomic/drain tail.

#define NPAIRS   (8 * 1024 * 1024)
#define NVEC     (NPAIRS / 2)          // 4194304 float4 per array
#define NTHR     1024
#define NBLK     296                   // 148 SMs * 2 CTAs, one resident wave
#define STRIDE   (NBLK * NTHR)         // 303104 (identical to R8 best run)
#define NWARP    (NTHR / 32)           // 32

// Per-block partials: {sumsq0, sumsq1, sumsq2, max_l0}
__device__ float4       g_partial[NBLK];
__device__ unsigned int g_count = 0;

__device__ __forceinline__ float bar_len(float a, float b) {
    float l = a - b;
    return isfinite(l) ? l : 0.0f;
}

__device__ __forceinline__ void warp_reduce4(float& s0, float& s1, float& s2, float& m) {
    #pragma unroll
    for (int o = 16; o > 0; o >>= 1) {
        s0 += __shfl_down_sync(0xFFFFFFFFu, s0, o);
        s1 += __shfl_down_sync(0xFFFFFFFFu, s1, o);
        s2 += __shfl_down_sync(0xFFFFFFFFu, s2, o);
        m   = fmaxf(m, __shfl_down_sync(0xFFFFFFFFu, m, o));
    }
}

__global__ void __launch_bounds__(NTHR, 2)
toploss_fused(const float4* __restrict__ d0,
              const float4* __restrict__ d1,
              const float4* __restrict__ d2,
              float* __restrict__ out) {
    float s0 = 0.0f, s1 = 0.0f, s2 = 0.0f;
    float m = -CUDART_INF_F;

    for (int i = blockIdx.x * NTHR + threadIdx.x; i < NVEC; i += STRIDE) {
        // issue all three loads up front, then compute (R8-proven pattern)
        float4 v0 = d0[i];
        float4 v1 = d1[i];
        float4 v2 = d2[i];

        float la = bar_len(v0.x, v0.y);
        float lb = bar_len(v0.z, v0.w);
        s0 = fmaf(la, la, s0);
        s0 = fmaf(lb, lb, s0);
        m  = fmaxf(m, fmaxf(la, lb));

        la = bar_len(v1.x, v1.y);
        lb = bar_len(v1.z, v1.w);
        s1 = fmaf(la, la, s1);
        s1 = fmaf(lb, lb, s1);

        la = bar_len(v2.x, v2.y);
        lb = bar_len(v2.z, v2.w);
        s2 = fmaf(la, la, s2);
        s2 = fmaf(lb, lb, s2);
    }

    // ---- intra-block reduce ----
    warp_reduce4(s0, s1, s2, m);

    __shared__ float sh0[NWARP], sh1[NWARP], sh2[NWARP], shm[NWARP];
    int lane = threadIdx.x & 31;
    int warp = threadIdx.x >> 5;
    if (lane == 0) { sh0[warp] = s0; sh1[warp] = s1; sh2[warp] = s2; shm[warp] = m; }
    __syncthreads();

    if (warp == 0) {
        s0 = sh0[lane];
        s1 = sh1[lane];
        s2 = sh2[lane];
        m  = shm[lane];
        #pragma unroll
        for (int o = 16; o > 0; o >>= 1) {   // NWARP == 32
            s0 += __shfl_down_sync(0xFFFFFFFFu, s0, o);
            s1 += __shfl_down_sync(0xFFFFFFFFu, s1, o);
            s2 += __shfl_down_sync(0xFFFFFFFFu, s2, o);
            m   = fmaxf(m, __shfl_down_sync(0xFFFFFFFFu, m, o));
        }
        if (lane == 0) {
            g_partial[blockIdx.x] = make_float4(s0, s1, s2, m);
            __threadfence();  // release: partial visible before counter bump
        }
    }
    __syncthreads();

    // ---- last-CTA finalize ----
    __shared__ unsigned int s_ticket;
    if (threadIdx.x == 0) s_ticket = atomicAdd(&g_count, 1u);
    __syncthreads();
    if (s_ticket != NBLK - 1) return;

    s0 = 0.0f; s1 = 0.0f; s2 = 0.0f; m = -CUDART_INF_F;
    if (threadIdx.x < NBLK) {
        float4 p = g_partial[threadIdx.x];
        s0 = p.x; s1 = p.y; s2 = p.z; m = p.w;
    }

    warp_reduce4(s0, s1, s2, m);

    if (lane == 0) { sh0[warp] = s0; sh1[warp] = s1; sh2[warp] = s2; shm[warp] = m; }
    __syncthreads();

    if (warp == 0) {
        s0 = sh0[lane];
        s1 = sh1[lane];
        s2 = sh2[lane];
        m  = shm[lane];
        #pragma unroll
        for (int o = 16; o > 0; o >>= 1) {
            s0 += __shfl_down_sync(0xFFFFFFFFu, s0, o);
            s1 += __shfl_down_sync(0xFFFFFFFFu, s1, o);
            s2 += __shfl_down_sync(0xFFFFFFFFu, s2, o);
            m   = fmaxf(m, __shfl_down_sync(0xFFFFFFFFu, m, o));
        }
        if (lane == 0) {
            float m2  = m * m;
            float t01 = 1.0f - m2;
            float t0  = s0 - m2;
            out[0] = t01 + t0 + s1 + s2;  // loss
            out[1] = t01;
            out[2] = t0;
            out[3] = s1;
            out[4] = s2;
            g_count = 0;                  // reset for next graph replay
        }
    }
}

extern "C" void kernel_launch(void* const* d_in, const int* in_sizes, int n_in,
                              void* d_out, int out_size) {
    const float4* d0 = (const float4*)d_in[0];
    const float4* d1 = (const float4*)d_in[1];
    const float4* d2 = (const float4*)d_in[2];
    toploss_fused<<<NBLK, NTHR>>>(d0, d1, d2, (float*)d_out);
}

// round 15
// speedup vs baseline: 1.5212x; 1.0044x over previous
#include <cuda_runtime.h>
#include <math.h>
#include <math_constants.h>

// TopLoss: three 8M x 2 fp32 diagrams.
//   l = dgm[:,0] - dgm[:,1], non-finite -> 0
//   top1 = max(l0); t01 = 1 - top1^2; t0 = sumsq(l0) - top1^2
//   t1 = sumsq(l1); t2 = sumsq(l2); loss = t01 + t0 + t1 + t2
// Output: (loss, t01, t0, t1, t2) as 5 fp32.
//
// FINAL (best measured: 34.9 us, DRAM 71.5% SOL, 5.85 TB/s).
// Single fused kernel, occupancy-first (regs capped via launch_bounds -> 64
// warps/SM, 4 CTAs x 512 threads). 3 batched LDG.128 per grid-stride
// iteration; last-CTA threadfence finalize with self-resetting counter.
// Explored and rejected: 6-LDG unroll at lower occ (39.1), cp.async SMEM
// pipeline (55.0, LDGSTS issue-rate bound), d0 prefetch (38.8, broke ptxas
// load batching), 1024-thread CTAs (36.3, barrier cost).

#define NPAIRS   (8 * 1024 * 1024)
#define NVEC     (NPAIRS / 2)          // 4194304 float4 per array
#define NTHR     512
#define NBLK     592                   // 148 SMs * 4 CTAs, one resident wave
#define STRIDE   (NBLK * NTHR)         // 303104
#define NWARP    (NTHR / 32)           // 16

// Per-block partials: {sumsq0, sumsq1, sumsq2, max_l0}
__device__ float4       g_partial[NBLK];
__device__ unsigned int g_count = 0;

__device__ __forceinline__ float bar_len(float a, float b) {
    float l = a - b;
    return isfinite(l) ? l : 0.0f;
}

__device__ __forceinline__ void warp_reduce4(float& s0, float& s1, float& s2, float& m) {
    #pragma unroll
    for (int o = 16; o > 0; o >>= 1) {
        s0 += __shfl_down_sync(0xFFFFFFFFu, s0, o);
        s1 += __shfl_down_sync(0xFFFFFFFFu, s1, o);
        s2 += __shfl_down_sync(0xFFFFFFFFu, s2, o);
        m   = fmaxf(m, __shfl_down_sync(0xFFFFFFFFu, m, o));
    }
}

__global__ void __launch_bounds__(NTHR, 4)
toploss_fused(const float4* __restrict__ d0,
              const float4* __restrict__ d1,
              const float4* __restrict__ d2,
              float* __restrict__ out) {
    float s0 = 0.0f, s1 = 0.0f, s2 = 0.0f;
    float m = -CUDART_INF_F;

    for (int i = blockIdx.x * NTHR + threadIdx.x; i < NVEC; i += STRIDE) {
        // issue all three loads up front, then compute
        float4 v0 = d0[i];
        float4 v1 = d1[i];
        float4 v2 = d2[i];

        float la = bar_len(v0.x, v0.y);
        float lb = bar_len(v0.z, v0.w);
        s0 = fmaf(la, la, s0);
        s0 = fmaf(lb, lb, s0);
        m  = fmaxf(m, fmaxf(la, lb));

        la = bar_len(v1.x, v1.y);
        lb = bar_len(v1.z, v1.w);
        s1 = fmaf(la, la, s1);
        s1 = fmaf(lb, lb, s1);

        la = bar_len(v2.x, v2.y);
        lb = bar_len(v2.z, v2.w);
        s2 = fmaf(la, la, s2);
        s2 = fmaf(lb, lb, s2);
    }

    // ---- intra-block reduce ----
    warp_reduce4(s0, s1, s2, m);

    __shared__ float sh0[NWARP], sh1[NWARP], sh2[NWARP], shm[NWARP];
    int lane = threadIdx.x & 31;
    int warp = threadIdx.x >> 5;
    if (lane == 0) { sh0[warp] = s0; sh1[warp] = s1; sh2[warp] = s2; shm[warp] = m; }
    __syncthreads();

    if (warp == 0) {
        s0 = (lane < NWARP) ? sh0[lane] : 0.0f;
        s1 = (lane < NWARP) ? sh1[lane] : 0.0f;
        s2 = (lane < NWARP) ? sh2[lane] : 0.0f;
        m  = (lane < NWARP) ? shm[lane] : -CUDART_INF_F;
        #pragma unroll
        for (int o = 8; o > 0; o >>= 1) {   // NWARP == 16
            s0 += __shfl_down_sync(0xFFFFFFFFu, s0, o);
            s1 += __shfl_down_sync(0xFFFFFFFFu, s1, o);
            s2 += __shfl_down_sync(0xFFFFFFFFu, s2, o);
            m   = fmaxf(m, __shfl_down_sync(0xFFFFFFFFu, m, o));
        }
        if (lane == 0) {
            g_partial[blockIdx.x] = make_float4(s0, s1, s2, m);
            __threadfence();  // release: partial visible before counter bump
        }
    }
    __syncthreads();

    // ---- last-CTA finalize ----
    __shared__ unsigned int s_ticket;
    if (threadIdx.x == 0) s_ticket = atomicAdd(&g_count, 1u);
    __syncthreads();
    if (s_ticket != NBLK - 1) return;

    s0 = 0.0f; s1 = 0.0f; s2 = 0.0f; m = -CUDART_INF_F;
    for (int i = threadIdx.x; i < NBLK; i += NTHR) {
        float4 p = g_partial[i];
        s0 += p.x; s1 += p.y; s2 += p.z;
        m = fmaxf(m, p.w);
    }

    warp_reduce4(s0, s1, s2, m);

    if (lane == 0) { sh0[warp] = s0; sh1[warp] = s1; sh2[warp] = s2; shm[warp] = m; }
    __syncthreads();

    if (warp == 0) {
        s0 = (lane < NWARP) ? sh0[lane] : 0.0f;
        s1 = (lane < NWARP) ? sh1[lane] : 0.0f;
        s2 = (lane < NWARP) ? sh2[lane] : 0.0f;
        m  = (lane < NWARP) ? shm[lane] : -CUDART_INF_F;
        #pragma unroll
        for (int o = 8; o > 0; o >>= 1) {
            s0 += __shfl_down_sync(0xFFFFFFFFu, s0, o);
            s1 += __shfl_down_sync(0xFFFFFFFFu, s1, o);
            s2 += __shfl_down_sync(0xFFFFFFFFu, s2, o);
            m   = fmaxf(m, __shfl_down_sync(0xFFFFFFFFu, m, o));
        }
        if (lane == 0) {
            float m2  = m * m;
            float t01 = 1.0f - m2;
            float t0  = s0 - m2;
            out[0] = t01 + t0 + s1 + s2;  // loss
            out[1] = t01;
            out[2] = t0;
            out[3] = s1;
            out[4] = s2;
            g_count = 0;                  // reset for next graph replay
        }
    }
}

extern "C" void kernel_launch(void* const* d_in, const int* in_sizes, int n_in,
                              void* d_out, int out_size) {
    const float4* d0 = (const float4*)d_in[0];
    const float4* d1 = (const float4*)d_in[1];
    const float4* d2 = (const float4*)d_in[2];
    toploss_fused<<<NBLK, NTHR>>>(d0, d1, d2, (float*)d_out);
}